// round 2
// baseline (speedup 1.0000x reference)
#include <cuda_runtime.h>
#include <cstdint>

// RnCLoss: N=4096 samples, D=256 features, scalar fp32 loss output.
//
// loss = -1/(n(n-1)) * sum_{i != k} [ logits[i,k] - log(denom[i,k]) ]
//   logits = (F F^T) / tau
//   denom[i,k] = sum_{j != i} exp(logits[i,j]) * [ fl|l_j - l_i| >= fl|l_k - l_i| ]
//
// Labels are scalar. d(m) = fl(ls[m] - li) is monotone over the sorted labels,
// and fl(l_i-l_j) == -fl(l_j-l_i) exactly, so the reference indicator set
// {j : fl|l_i-l_j| >= t} == {m : d(m) <= -t} U {m : d(m) >= t} for t > 0,
// found by two binary searches on d(m). One global label sort serves all rows.

#define NN 4096
#define DD 256

// -------------------- device scratch (no allocations allowed) ---------------
__device__ float g_S[(size_t)NN * NN];   // logits (already divided by tau), 64 MB
__device__ float g_labels[NN];           // normalized labels, original order
__device__ float g_ls[NN];               // labels sorted ascending
__device__ int   g_ord[NN];              // g_ls[m] == g_labels[g_ord[m]]
__device__ float g_partials[NN];         // per-row partial sums

// epoch may arrive as int32/int64 (small value) or float32 — disambiguate.
__device__ __forceinline__ float read_epoch(const void* p) {
    int ei = *(const int*)p;
    if (ei >= 0 && ei <= 1000000) return (float)ei;
    return *(const float*)p;
}

// -------------------- kernel 1: labels + bitonic sort -----------------------
__global__ void __launch_bounds__(1024) sort_kernel(
    const float* __restrict__ origin,
    const float* __restrict__ mean,
    const float* __restrict__ stdv)
{
    __shared__ float key[NN];
    __shared__ int   val[NN];
    int t = threadIdx.x;
    float mu = mean[0];
    float sd = stdv[0] + 1e-8f;
    for (int i = t; i < NN; i += 1024) {
        float l = (origin[i] - mu) / sd;
        key[i] = l; val[i] = i;
        g_labels[i] = l;
    }
    __syncthreads();
    for (int k = 2; k <= NN; k <<= 1) {
        for (int j = k >> 1; j > 0; j >>= 1) {
            for (int i = t; i < NN; i += 1024) {
                int ixj = i ^ j;
                if (ixj > i) {
                    bool up = ((i & k) == 0);
                    float a = key[i], b = key[ixj];
                    if ((a > b) == up) {
                        key[i] = b; key[ixj] = a;
                        int tv = val[i]; val[i] = val[ixj]; val[ixj] = tv;
                    }
                }
            }
            __syncthreads();
        }
    }
    for (int i = t; i < NN; i += 1024) { g_ls[i] = key[i]; g_ord[i] = val[i]; }
}

// -------------------- kernel 2: SGEMM S = (F F^T)/tau ------------------------
#define BM 128
#define BN 128
#define BK 16

__global__ void __launch_bounds__(256) gemm_kernel(
    const float* __restrict__ F, const void* __restrict__ epoch_ptr)
{
    __shared__ float As[BK][BM];
    __shared__ float Bs[BK][BN];

    int i0 = blockIdx.y * BM;
    int j0 = blockIdx.x * BN;
    int t  = threadIdx.x;
    int ty = t >> 4;        // 0..15
    int tx = t & 15;        // 0..15

    float epoch = read_epoch(epoch_ptr);
    float tau = 1.0f - 0.9f * epoch / 100.0f;
    float itau = 1.0f / tau;

    float acc[8][8];
#pragma unroll
    for (int r = 0; r < 8; r++)
#pragma unroll
        for (int c = 0; c < 8; c++) acc[r][c] = 0.0f;

    for (int kk = 0; kk < DD; kk += BK) {
#pragma unroll
        for (int rr = 0; rr < 2; rr++) {
            int q = t + rr * 256;      // 0..511
            int m  = q >> 2;           // 0..127
            int kg = q & 3;            // 0..3  (4 k-values each)
            float4 va = *(const float4*)&F[(i0 + m) * DD + kk + kg * 4];
            As[kg * 4 + 0][m] = va.x;
            As[kg * 4 + 1][m] = va.y;
            As[kg * 4 + 2][m] = va.z;
            As[kg * 4 + 3][m] = va.w;
            float4 vb = *(const float4*)&F[(j0 + m) * DD + kk + kg * 4];
            Bs[kg * 4 + 0][m] = vb.x;
            Bs[kg * 4 + 1][m] = vb.y;
            Bs[kg * 4 + 2][m] = vb.z;
            Bs[kg * 4 + 3][m] = vb.w;
        }
        __syncthreads();
#pragma unroll
        for (int k = 0; k < BK; k++) {
            float a[8], b[8];
#pragma unroll
            for (int r = 0; r < 8; r++) a[r] = As[k][ty * 8 + r];
#pragma unroll
            for (int c = 0; c < 8; c++) b[c] = Bs[k][tx * 8 + c];
#pragma unroll
            for (int r = 0; r < 8; r++)
#pragma unroll
                for (int c = 0; c < 8; c++) acc[r][c] += a[r] * b[c];
        }
        __syncthreads();
    }

#pragma unroll
    for (int r = 0; r < 8; r++) {
        int row = i0 + ty * 8 + r;
        float4 v0, v1;
        v0.x = acc[r][0] * itau; v0.y = acc[r][1] * itau;
        v0.z = acc[r][2] * itau; v0.w = acc[r][3] * itau;
        v1.x = acc[r][4] * itau; v1.y = acc[r][5] * itau;
        v1.z = acc[r][6] * itau; v1.w = acc[r][7] * itau;
        float* dst = &g_S[(size_t)row * NN + j0 + tx * 8];
        *(float4*)(dst)     = v0;
        *(float4*)(dst + 4) = v1;
    }
}

// -------------------- kernel 3: per-row denom + partial loss -----------------
// dyn smem: s_ls[NN] | s_row[NN] | s_p[NN] | s_red[1024]
#define ROW_THREADS 256
#define ROW_SMEM_FLOATS (3 * NN + 1024)

__global__ void __launch_bounds__(ROW_THREADS) row_kernel()
{
    extern __shared__ float sm[];
    float* s_ls  = sm;
    float* s_row = sm + NN;
    float* s_p   = sm + 2 * NN;
    float* s_red = sm + 3 * NN;

    const int i = blockIdx.x;
    const int t = threadIdx.x;

    for (int m = t; m < NN; m += ROW_THREADS) {
        s_ls[m]  = g_ls[m];
        s_row[m] = g_S[(size_t)i * NN + m];
    }
    __syncthreads();

    // exp(logits) in label-sorted order
    for (int m = t; m < NN; m += ROW_THREADS) {
        s_p[m] = __expf(s_row[g_ord[m]]);
    }
    __syncthreads();

    // inclusive scan of s_p (256 threads x 16-element chunks)
    const int CH = NN / ROW_THREADS;   // 16
    float run = 0.0f;
#pragma unroll
    for (int q = 0; q < CH; q++) { run += s_p[t * CH + q]; s_p[t * CH + q] = run; }
    int lane = t & 31, warp = t >> 5;
    float v = run;
#pragma unroll
    for (int d = 1; d < 32; d <<= 1) {
        float u = __shfl_up_sync(0xFFFFFFFFu, v, d);
        if (lane >= d) v += u;
    }
    if (lane == 31) s_red[warp] = v;
    __syncthreads();
    if (warp == 0 && lane < 8) {
        float w = s_red[lane];
#pragma unroll
        for (int d = 1; d < 8; d <<= 1) {
            float u = __shfl_up_sync(0xFFu, w, d);
            if (lane >= d) w += u;
        }
        s_red[lane] = w;
    }
    __syncthreads();
    float off = (warp > 0 ? s_red[warp - 1] : 0.0f) + (v - run);
#pragma unroll
    for (int q = 0; q < CH; q++) s_p[t * CH + q] += off;
    __syncthreads();

    const float T  = s_p[NN - 1];
    const float li = g_labels[i];
    const float e_self = __expf(s_row[i]);

    float acc = 0.0f;
    for (int k = t; k < NN; k += ROW_THREADS) {
        if (k == i) continue;
        float tthr = fabsf(g_labels[k] - li);
        float denom;
        if (tthr == 0.0f) {
            denom = T - e_self;
        } else {
            // d(m) = fl(ls[m] - li) is monotone non-decreasing in m.
            // left: count of m with d(m) <= -tthr   (upper_bound on -tthr)
            float nt = -tthr;
            int lo = 0, hi = NN;
            while (lo < hi) {
                int m = (lo + hi) >> 1;
                if ((s_ls[m] - li) <= nt) lo = m + 1; else hi = m;
            }
            float left = (lo == 0) ? 0.0f : s_p[lo - 1];
            // right: first m with d(m) >= tthr      (lower_bound on tthr)
            int lo2 = 0, hi2 = NN;
            while (lo2 < hi2) {
                int m = (lo2 + hi2) >> 1;
                if ((s_ls[m] - li) < tthr) lo2 = m + 1; else hi2 = m;
            }
            float right = T - ((lo2 == 0) ? 0.0f : s_p[lo2 - 1]);
            denom = left + right;
        }
        acc += s_row[k] - __logf(denom);
    }

    __syncthreads();
    s_red[t] = acc;
    __syncthreads();
    for (int s = ROW_THREADS / 2; s > 0; s >>= 1) {
        if (t < s) s_red[t] += s_red[t + s];
        __syncthreads();
    }
    if (t == 0) g_partials[i] = s_red[0];
}

// -------------------- kernel 4: finalize -------------------------------------
__global__ void __launch_bounds__(256) finalize_kernel(float* __restrict__ out)
{
    __shared__ double sh[256];
    int t = threadIdx.x;
    double a = 0.0;
    for (int i = t; i < NN; i += 256) a += (double)g_partials[i];
    sh[t] = a;
    __syncthreads();
    for (int s = 128; s > 0; s >>= 1) {
        if (t < s) sh[t] += sh[t + s];
        __syncthreads();
    }
    if (t == 0) out[0] = (float)(-sh[0] / ((double)NN * (double)(NN - 1)));
}

// -------------------- launch --------------------------------------------------
extern "C" void kernel_launch(void* const* d_in, const int* in_sizes, int n_in,
                              void* d_out, int out_size)
{
    const float* F      = (const float*)d_in[0];
    const float* origin = (const float*)d_in[1];
    const float* mean   = (const float*)d_in[2];
    const float* stdv   = (const float*)d_in[3];
    const void*  epoch  = d_in[4];

    sort_kernel<<<1, 1024>>>(origin, mean, stdv);

    dim3 ggrid(NN / BN, NN / BM);
    gemm_kernel<<<ggrid, 256>>>(F, epoch);

    size_t smem = ROW_SMEM_FLOATS * sizeof(float);   // 53248 B
    cudaFuncSetAttribute(row_kernel, cudaFuncAttributeMaxDynamicSharedMemorySize, (int)smem);
    row_kernel<<<NN, ROW_THREADS, smem>>>();

    finalize_kernel<<<1, 256>>>((float*)d_out);
}

// round 3
// speedup vs baseline: 2.9233x; 2.9233x over previous
#include <cuda_runtime.h>
#include <cuda_bf16.h>
#include <cstdint>

// RnCLoss: N=4096, D=256, scalar fp32 loss.
// loss = -1/(n(n-1)) * sum_{i != k} [ logits[i,k] - log(denom[i,k]) ]
//   logits = (F F^T)/tau ;  denom over label-distance indicator.
//
// Pipeline: convert F->bf16, bitonic label sort, bf16 HMMA GEMM over
// lower-triangle tiles (writes tile + transpose), per-row kernel that walks
// sorted label positions (1 binary search/position), finalize.

#define NN 4096
#define DD 256

__device__ float g_S[(size_t)NN * NN];            // logits/tau, 64 MB
__device__ __align__(16) __nv_bfloat16 g_Fb[(size_t)NN * DD];
__device__ float g_labels[NN];
__device__ float g_ls[NN];
__device__ int   g_ord[NN];
__device__ float g_partials[NN];

__device__ __forceinline__ float read_epoch(const void* p) {
    int ei = *(const int*)p;
    if (ei >= 0 && ei <= 1000000) return (float)ei;
    return *(const float*)p;
}

// ---------------- kernel 0: fp32 -> bf16 convert -----------------------------
__global__ void __launch_bounds__(256) convert_kernel(const float* __restrict__ F) {
    int base = (blockIdx.x * 256 + threadIdx.x) * 8;
    float4 v0 = *(const float4*)(F + base);
    float4 v1 = *(const float4*)(F + base + 4);
    __nv_bfloat162 b0 = __floats2bfloat162_rn(v0.x, v0.y);
    __nv_bfloat162 b1 = __floats2bfloat162_rn(v0.z, v0.w);
    __nv_bfloat162 b2 = __floats2bfloat162_rn(v1.x, v1.y);
    __nv_bfloat162 b3 = __floats2bfloat162_rn(v1.z, v1.w);
    uint4 packed;
    packed.x = *(uint32_t*)&b0; packed.y = *(uint32_t*)&b1;
    packed.z = *(uint32_t*)&b2; packed.w = *(uint32_t*)&b3;
    *(uint4*)(g_Fb + base) = packed;
}

// ---------------- kernel 1: labels + bitonic sort ----------------------------
__global__ void __launch_bounds__(1024) sort_kernel(
    const float* __restrict__ origin,
    const float* __restrict__ mean,
    const float* __restrict__ stdv)
{
    __shared__ float key[NN];
    __shared__ int   val[NN];
    int t = threadIdx.x;
    float mu = mean[0];
    float sd = stdv[0] + 1e-8f;
    for (int i = t; i < NN; i += 1024) {
        float l = (origin[i] - mu) / sd;
        key[i] = l; val[i] = i;
        g_labels[i] = l;
    }
    __syncthreads();
    for (int k = 2; k <= NN; k <<= 1) {
        for (int j = k >> 1; j > 0; j >>= 1) {
            for (int i = t; i < NN; i += 1024) {
                int ixj = i ^ j;
                if (ixj > i) {
                    bool up = ((i & k) == 0);
                    float a = key[i], b = key[ixj];
                    if ((a > b) == up) {
                        key[i] = b; key[ixj] = a;
                        int tv = val[i]; val[i] = val[ixj]; val[ixj] = tv;
                    }
                }
            }
            __syncthreads();
        }
    }
    for (int i = t; i < NN; i += 1024) { g_ls[i] = key[i]; g_ord[i] = val[i]; }
}

// ---------------- kernel 2: bf16 HMMA GEMM (lower-triangle tiles) ------------
#define ASTRIDE 40      // 32 bf16 payload + 8 pad -> 80B row, conflict-free LDSM

__device__ __forceinline__ uint32_t sptr(const void* p) {
    return (uint32_t)__cvta_generic_to_shared(p);
}
__device__ __forceinline__ void ldsm4(uint32_t& r0, uint32_t& r1, uint32_t& r2,
                                      uint32_t& r3, uint32_t addr) {
    asm volatile("ldmatrix.sync.aligned.m8n8.x4.shared.b16 {%0,%1,%2,%3}, [%4];"
                 : "=r"(r0), "=r"(r1), "=r"(r2), "=r"(r3) : "r"(addr));
}
__device__ __forceinline__ void mma16816(float* c, uint32_t a0, uint32_t a1,
                                         uint32_t a2, uint32_t a3,
                                         uint32_t b0, uint32_t b1) {
    asm volatile(
        "mma.sync.aligned.m16n8k16.row.col.f32.bf16.bf16.f32 "
        "{%0,%1,%2,%3}, {%4,%5,%6,%7}, {%8,%9}, {%0,%1,%2,%3};"
        : "+f"(c[0]), "+f"(c[1]), "+f"(c[2]), "+f"(c[3])
        : "r"(a0), "r"(a1), "r"(a2), "r"(a3), "r"(b0), "r"(b1));
}

__global__ void __launch_bounds__(256) gemm_kernel(const void* __restrict__ epoch_ptr)
{
    // smem: loader tiles (2 * 128 * 40 * 2B = 20480B), reused as fp32 transpose
    // staging (32 * 132 * 4B = 16896B) in the epilogue.
    __shared__ __align__(16) unsigned char smem_buf[2 * 128 * ASTRIDE * 2];
    __nv_bfloat16* sA = (__nv_bfloat16*)smem_buf;
    __nv_bfloat16* sB = sA + 128 * ASTRIDE;
    float* tr = (float*)smem_buf;

    // decode lower-triangle tile index
    int b = blockIdx.x;
    int bi = (int)((sqrtf(8.0f * b + 1.0f) - 1.0f) * 0.5f);
    while ((bi + 1) * (bi + 2) / 2 <= b) bi++;
    while (bi * (bi + 1) / 2 > b) bi--;
    int bj = b - bi * (bi + 1) / 2;
    int i0 = bi * 128, j0 = bj * 128;

    int t = threadIdx.x;
    int lane = t & 31, w = t >> 5;
    int warp_m = w & 1;      // 2 x 64 rows
    int warp_n = w >> 1;     // 4 x 32 cols

    float epoch = read_epoch(epoch_ptr);
    float itau = 1.0f / (1.0f - 0.9f * epoch / 100.0f);

    float acc[4][4][4];
#pragma unroll
    for (int mb = 0; mb < 4; mb++)
#pragma unroll
        for (int nb = 0; nb < 4; nb++)
#pragma unroll
            for (int r = 0; r < 4; r++) acc[mb][nb][r] = 0.0f;

    for (int kk = 0; kk < DD; kk += 32) {
#pragma unroll
        for (int s = 0; s < 2; s++) {
            int idx = t + s * 256;
            int r = idx >> 2, cg = idx & 3;
            uint4 va = *(const uint4*)(g_Fb + (size_t)(i0 + r) * DD + kk + cg * 8);
            *(uint4*)(sA + r * ASTRIDE + cg * 8) = va;
            uint4 vb = *(const uint4*)(g_Fb + (size_t)(j0 + r) * DD + kk + cg * 8);
            *(uint4*)(sB + r * ASTRIDE + cg * 8) = vb;
        }
        __syncthreads();

#pragma unroll
        for (int ks = 0; ks < 2; ks++) {
            int kb = ks * 16;
            uint32_t af[4][4];
#pragma unroll
            for (int mb = 0; mb < 4; mb++) {
                int row = warp_m * 64 + mb * 16 + (lane & 7) + ((lane >> 3) & 1) * 8;
                int col = kb + (lane >> 4) * 8;
                ldsm4(af[mb][0], af[mb][1], af[mb][2], af[mb][3],
                      sptr(sA + row * ASTRIDE + col));
            }
            uint32_t bf[2][4];
#pragma unroll
            for (int hb = 0; hb < 2; hb++) {
                int n = warp_n * 32 + hb * 16 + ((lane >> 4) & 1) * 8 + (lane & 7);
                int col = kb + ((lane >> 3) & 1) * 8;
                ldsm4(bf[hb][0], bf[hb][1], bf[hb][2], bf[hb][3],
                      sptr(sB + n * ASTRIDE + col));
            }
#pragma unroll
            for (int mb = 0; mb < 4; mb++)
#pragma unroll
                for (int nb = 0; nb < 4; nb++) {
                    int hb = nb >> 1, pr = nb & 1;
                    mma16816(acc[mb][nb], af[mb][0], af[mb][1], af[mb][2], af[mb][3],
                             bf[hb][pr * 2], bf[hb][pr * 2 + 1]);
                }
        }
        __syncthreads();
    }

    // scale
#pragma unroll
    for (int mb = 0; mb < 4; mb++)
#pragma unroll
        for (int nb = 0; nb < 4; nb++)
#pragma unroll
            for (int r = 0; r < 4; r++) acc[mb][nb][r] *= itau;

    // direct store of (i0, j0) tile
#pragma unroll
    for (int mb = 0; mb < 4; mb++)
#pragma unroll
        for (int nb = 0; nb < 4; nb++) {
            int row = warp_m * 64 + mb * 16 + (lane >> 2);
            int col = warp_n * 32 + nb * 8 + (lane & 3) * 2;
            float2 v01 = make_float2(acc[mb][nb][0], acc[mb][nb][1]);
            float2 v23 = make_float2(acc[mb][nb][2], acc[mb][nb][3]);
            *(float2*)&g_S[(size_t)(i0 + row) * NN + j0 + col] = v01;
            *(float2*)&g_S[(size_t)(i0 + row + 8) * NN + j0 + col] = v23;
        }

    // transposed store of (j0, i0) tile via smem staging (coalesced)
    if (bi != bj) {
        __syncthreads();   // done with sA/sB
#pragma unroll
        for (int c = 0; c < 4; c++) {
            if (warp_n == c) {
#pragma unroll
                for (int mb = 0; mb < 4; mb++)
#pragma unroll
                    for (int nb = 0; nb < 4; nb++) {
                        int row = warp_m * 64 + mb * 16 + (lane >> 2);
                        int cl = nb * 8 + (lane & 3) * 2;
                        tr[cl * 132 + row]           = acc[mb][nb][0];
                        tr[(cl + 1) * 132 + row]     = acc[mb][nb][1];
                        tr[cl * 132 + row + 8]       = acc[mb][nb][2];
                        tr[(cl + 1) * 132 + row + 8] = acc[mb][nb][3];
                    }
            }
            __syncthreads();
#pragma unroll
            for (int s = 0; s < 4; s++) {
                int q = t + s * 256;
                int cl = q >> 5, c4 = q & 31;
                float4 v = *(float4*)&tr[cl * 132 + c4 * 4];
                *(float4*)&g_S[(size_t)(j0 + c * 32 + cl) * NN + i0 + c4 * 4] = v;
            }
            __syncthreads();
        }
    }
}

// ---------------- kernel 3: per-row denom + partial loss ---------------------
// Iterate over sorted label positions q: same-side boundary is q (+- tie walk),
// opposite boundary is ONE binary search over a half range.
#define ROW_THREADS 256
#define ROW_SMEM_FLOATS (2 * NN + 256)

__global__ void __launch_bounds__(ROW_THREADS) row_kernel()
{
    extern __shared__ float sm[];
    float* s_ls  = sm;             // sorted labels
    float* s_p   = sm + NN;        // scanned exp (label-sorted order)
    float* s_red = sm + 2 * NN;    // reductions
    __shared__ int   sh_pi;
    __shared__ float sh_self;

    const int i = blockIdx.x;
    const int t = threadIdx.x;
    const float* Srow = &g_S[(size_t)i * NN];

    // pass 1: rowsum (coalesced float4) + self logit
    if (t == 0) sh_self = Srow[i];
    float rs = 0.0f;
    for (int m4 = t; m4 < NN / 4; m4 += ROW_THREADS) {
        float4 v = *(const float4*)(Srow + m4 * 4);
        rs += v.x + v.y + v.z + v.w;
    }

    // pass 2: sorted labels + exp(logits) gathered into sorted order
    for (int m = t; m < NN; m += ROW_THREADS) {
        s_ls[m] = g_ls[m];
        int src = g_ord[m];
        if (src == i) sh_pi = m;
        s_p[m] = __expf(Srow[src]);
    }
    __syncthreads();

    // inclusive scan of s_p
    const int CH = NN / ROW_THREADS;   // 16
    float run = 0.0f;
#pragma unroll
    for (int q = 0; q < CH; q++) { run += s_p[t * CH + q]; s_p[t * CH + q] = run; }
    int lane = t & 31, warp = t >> 5;
    float v = run;
#pragma unroll
    for (int d = 1; d < 32; d <<= 1) {
        float u = __shfl_up_sync(0xFFFFFFFFu, v, d);
        if (lane >= d) v += u;
    }
    if (lane == 31) s_red[warp] = v;
    __syncthreads();
    if (warp == 0 && lane < 8) {
        float wv = s_red[lane];
#pragma unroll
        for (int d = 1; d < 8; d <<= 1) {
            float u = __shfl_up_sync(0xFFu, wv, d);
            if (lane >= d) wv += u;
        }
        s_red[lane] = wv;
    }
    __syncthreads();
    float off = (warp > 0 ? s_red[warp - 1] : 0.0f) + (v - run);
#pragma unroll
    for (int q = 0; q < CH; q++) s_p[t * CH + q] += off;
    __syncthreads();

    const float T  = s_p[NN - 1];
    const int   pi = sh_pi;
    const float li = s_ls[pi];
    const float e_self = __expf(sh_self);

    float logsum = 0.0f;
    for (int q = t; q < NN; q += ROW_THREADS) {
        if (q == pi) continue;
        float dq = s_ls[q] - li;         // monotone in q; fl(l_q - l_i)
        float denom;
        if (dq == 0.0f) {
            denom = T - e_self;          // threshold 0 -> full off-diag sum
        } else if (dq > 0.0f) {
            // same-side boundary: first m with d(m) >= dq (tie walk back)
            int lo2 = q;
            while (lo2 > 0 && (s_ls[lo2 - 1] - li) >= dq) lo2--;
            // opposite: count of m in [0, pi) with d(m) <= -dq
            float nt = -dq;
            int a = 0, bnd = pi;
            while (a < bnd) {
                int m = (a + bnd) >> 1;
                if ((s_ls[m] - li) <= nt) a = m + 1; else bnd = m;
            }
            float left  = a ? s_p[a - 1] : 0.0f;
            float right = T - s_p[lo2 - 1];   // lo2 >= pi+1 >= 1
            denom = left + right;
        } else {
            // same-side boundary: count of m with d(m) <= dq (tie walk fwd)
            int lo = q + 1;
            while (lo < NN && (s_ls[lo] - li) <= dq) lo++;
            // opposite: first m in [pi+1, NN) with d(m) >= -dq
            float tp = -dq;
            int a = pi + 1, bnd = NN;
            while (a < bnd) {
                int m = (a + bnd) >> 1;
                if ((s_ls[m] - li) < tp) a = m + 1; else bnd = m;
            }
            float left  = s_p[lo - 1];        // lo >= 1
            float right = T - s_p[a - 1];     // a >= pi+1 >= 1
            denom = left + right;
        }
        logsum += __logf(denom);
    }

    // reduce rs and logsum
    __syncthreads();
    s_red[t] = rs;
    __syncthreads();
    for (int s = ROW_THREADS / 2; s > 0; s >>= 1) {
        if (t < s) s_red[t] += s_red[t + s];
        __syncthreads();
    }
    float rowsum = s_red[0];
    __syncthreads();
    s_red[t] = logsum;
    __syncthreads();
    for (int s = ROW_THREADS / 2; s > 0; s >>= 1) {
        if (t < s) s_red[t] += s_red[t + s];
        __syncthreads();
    }
    if (t == 0) g_partials[i] = (rowsum - sh_self) - s_red[0];
}

// ---------------- kernel 4: finalize ----------------------------------------
__global__ void __launch_bounds__(256) finalize_kernel(float* __restrict__ out)
{
    __shared__ double sh[256];
    int t = threadIdx.x;
    double a = 0.0;
    for (int i = t; i < NN; i += 256) a += (double)g_partials[i];
    sh[t] = a;
    __syncthreads();
    for (int s = 128; s > 0; s >>= 1) {
        if (t < s) sh[t] += sh[t + s];
        __syncthreads();
    }
    if (t == 0) out[0] = (float)(-sh[0] / ((double)NN * (double)(NN - 1)));
}

// ---------------- launch -----------------------------------------------------
extern "C" void kernel_launch(void* const* d_in, const int* in_sizes, int n_in,
                              void* d_out, int out_size)
{
    const float* F      = (const float*)d_in[0];
    const float* origin = (const float*)d_in[1];
    const float* mean   = (const float*)d_in[2];
    const float* stdv   = (const float*)d_in[3];
    const void*  epoch  = d_in[4];

    convert_kernel<<<(NN * DD) / (256 * 8), 256>>>(F);
    sort_kernel<<<1, 1024>>>(origin, mean, stdv);

    gemm_kernel<<<32 * 33 / 2, 256>>>(epoch);

    size_t smem = ROW_SMEM_FLOATS * sizeof(float);
    row_kernel<<<NN, ROW_THREADS, smem>>>();

    finalize_kernel<<<1, 256>>>((float*)d_out);
}